// round 15
// baseline (speedup 1.0000x reference)
#include <cuda_runtime.h>
#include <cuda_bf16.h>
#include <cuda_fp16.h>
#include <math.h>
#include <stdint.h>

// Problem constants (fixed shapes per reference)
#define NNA 40000
#define NNB 40000
#define EED 400000
#define DD  256
#define HH  8
#define RPSTR 40004   // rowptr per-relation stride

// ---------------- scratch (static device globals; no allocation) ----------------
__device__ __half g_hA16[NNA * DD];
__device__ __half g_hB16[NNB * DD];
__device__ __half g_W16[2 * 65536];   // W fp16, [side][k][n]
__device__ float  g_al0[NNA * HH];
__device__ float  g_ar0[NNB * HH];
__device__ float  g_al1[NNB * HH];
__device__ float  g_ar1[NNA * HH];
__device__ float  g_al2[NNA * HH];
__device__ float  g_ar2[NNA * HH];
__device__ float  g_blA[NNA * HH];
__device__ float  g_blB[NNB * HH];
__device__ int    g_srcs[3 * EED];
__device__ int    g_cnt[3 * NNA];
__device__ int    g_rowptr[3 * RPSTR];
__device__ int    g_blocksum[128];

// ---------------- helpers ----------------
__device__ __forceinline__ float leaky02(float x) { return x > 0.f ? x : 0.2f * x; }

__device__ __forceinline__ uint32_t smem_u32(const void* p) {
    uint32_t a;
    asm("{ .reg .u64 t; cvta.to.shared.u64 t, %1; cvt.u32.u64 %0, t; }" : "=r"(a) : "l"(p));
    return a;
}
__device__ __forceinline__ void ldsm4(uint32_t* r, uint32_t a) {
    asm volatile("ldmatrix.sync.aligned.m8n8.x4.shared.b16 {%0,%1,%2,%3}, [%4];"
                 : "=r"(r[0]), "=r"(r[1]), "=r"(r[2]), "=r"(r[3]) : "r"(a));
}
__device__ __forceinline__ void ldsm4t(uint32_t* r, uint32_t a) {
    asm volatile("ldmatrix.sync.aligned.m8n8.x4.trans.shared.b16 {%0,%1,%2,%3}, [%4];"
                 : "=r"(r[0]), "=r"(r[1]), "=r"(r[2]), "=r"(r[3]) : "r"(a));
}
// fp16 x fp16 -> fp32 accumulate
__device__ __forceinline__ void mma16816h(float* d, const uint32_t* a, uint32_t b0, uint32_t b1) {
    asm volatile("mma.sync.aligned.m16n8k16.row.col.f32.f16.f16.f32 "
                 "{%0,%1,%2,%3}, {%4,%5,%6,%7}, {%8,%9}, {%0,%1,%2,%3};"
                 : "+f"(d[0]), "+f"(d[1]), "+f"(d[2]), "+f"(d[3])
                 : "r"(a[0]), "r"(a[1]), "r"(a[2]), "r"(a[3]), "r"(b0), "r"(b1));
}

// ---------------- W fp16 convert (runs once, tiny) ----------------
__global__ __launch_bounds__(256)
void wsplit_kernel(const float* __restrict__ WA, const float* __restrict__ WB,
                   __half* __restrict__ W16) {
    const float* W = blockIdx.y ? WB : WA;
    __half* o = W16 + blockIdx.y * 65536;
    int i = (blockIdx.x * 256 + threadIdx.x) * 4;   // grid.x = 64
    float4 v = __ldg((const float4*)(W + i));
    __half2 h01 = __floats2half2_rn(v.x, v.y);
    __half2 h23 = __floats2half2_rn(v.z, v.w);
    *(uint2*)(o + i) = make_uint2(*(uint32_t*)&h01, *(uint32_t*)&h23);
}

// ---------------- merged GEMM (A and B sides via blockIdx.z) -----------------------
#define ASTR 40
#define BSTR 72
__global__ __launch_bounds__(256)
void gemm_fused2(const float* __restrict__ xA, const float* __restrict__ xB,
                 const __half* __restrict__ W16,
                 const float* __restrict__ bA_, const float* __restrict__ bB_,
                 __half* __restrict__ hA16, __half* __restrict__ hB16,
                 const float* __restrict__ attn_l, const float* __restrict__ attn_r,
                 const float* __restrict__ rel_l_A, const float* __restrict__ rel_l_B,
                 float* __restrict__ al0, float* __restrict__ ar1,
                 float* __restrict__ al2, float* __restrict__ ar2,
                 float* __restrict__ blA,
                 float* __restrict__ ar0, float* __restrict__ al1,
                 float* __restrict__ blB) {
    __shared__ __half sAhi[128 * ASTR];
    __shared__ __half sBhi[32 * BSTR];
    __shared__ float sattn[5][64];
    __shared__ float sbias[64];
    __shared__ float spart[5][4][128];

    const int tid  = threadIdx.x;
    const int lane = tid & 31;
    const int wid  = tid >> 5;
    const int wm   = wid & 1;
    const int wn   = wid >> 1;
    const int row0 = blockIdx.x * 128;
    const int col0 = blockIdx.y * 64;
    const int M = NNA;

    const float* A; const float* bias; __half* C16;
    const __half* Bh;
    const float* vp[5]; float* op[5];
    if (blockIdx.z == 0) {
        A = xA; bias = bA_; C16 = hA16;
        Bh = W16;
        vp[0] = attn_l + 0;   op[0] = al0;
        vp[1] = attn_r + 256; op[1] = ar1;
        vp[2] = attn_l + 512; op[2] = al2;
        vp[3] = attn_r + 512; op[3] = ar2;
        vp[4] = rel_l_A;      op[4] = blA;
    } else {
        A = xB; bias = bB_; C16 = hB16;
        Bh = W16 + 65536;
        vp[0] = attn_r + 0;   op[0] = ar0;
        vp[1] = attn_l + 256; op[1] = al1;
        vp[2] = 0;            op[2] = 0;
        vp[3] = 0;            op[3] = 0;
        vp[4] = rel_l_B;      op[4] = blB;
    }

    if (tid < 64) sbias[tid] = __ldg(bias + col0 + tid);
#pragma unroll
    for (int v = 0; v < 5; v++)
        if (vp[v] && tid < 64) sattn[v][tid] = __ldg(vp[v] + col0 + tid);

    float acc[4][2][4];
#pragma unroll
    for (int i = 0; i < 4; i++)
#pragma unroll
        for (int j = 0; j < 2; j++)
#pragma unroll
            for (int k = 0; k < 4; k++) acc[i][j][k] = 0.f;

    float4 av[4];
    uint2 bvh[2];
#pragma unroll
    for (int p = 0; p < 4; p++) {
        int f = tid + 256 * p, r = f >> 3, c = (f & 7) * 4;
        int gr = row0 + r;
        av[p] = (gr < M) ? __ldg((const float4*)(A + (size_t)gr * 256 + c))
                         : make_float4(0.f, 0.f, 0.f, 0.f);
    }
#pragma unroll
    for (int p = 0; p < 2; p++) {
        int f = tid + 256 * p, r = f >> 4, c = (f & 15) * 4;
        bvh[p] = __ldg((const uint2*)(Bh + (size_t)r * 256 + col0 + c));
    }

    for (int kb = 0; kb < 8; kb++) {
#pragma unroll
        for (int p = 0; p < 4; p++) {
            int f = tid + 256 * p, r = f >> 3, c = (f & 7) * 4;
            __half2 h01 = __floats2half2_rn(av[p].x, av[p].y);
            __half2 h23 = __floats2half2_rn(av[p].z, av[p].w);
            *(uint2*)&sAhi[r * ASTR + c] = make_uint2(*(uint32_t*)&h01, *(uint32_t*)&h23);
        }
#pragma unroll
        for (int p = 0; p < 2; p++) {
            int f = tid + 256 * p, r = f >> 4, c = (f & 15) * 4;
            *(uint2*)&sBhi[r * BSTR + c] = bvh[p];
        }
        __syncthreads();

        if (kb < 7) {
            int k0 = (kb + 1) * 32;
#pragma unroll
            for (int p = 0; p < 4; p++) {
                int f = tid + 256 * p, r = f >> 3, c = (f & 7) * 4;
                int gr = row0 + r;
                av[p] = (gr < M) ? __ldg((const float4*)(A + (size_t)gr * 256 + k0 + c))
                                 : make_float4(0.f, 0.f, 0.f, 0.f);
            }
#pragma unroll
            for (int p = 0; p < 2; p++) {
                int f = tid + 256 * p, r = f >> 4, c = (f & 15) * 4;
                bvh[p] = __ldg((const uint2*)(Bh + (size_t)(k0 + r) * 256 + col0 + c));
            }
        }

#pragma unroll
        for (int kk = 0; kk < 32; kk += 16) {
            uint32_t ahi[4][4], bh[4];
            int arow = wm * 64 + (lane & 15);
            int acol = kk + ((lane >> 4) << 3);
#pragma unroll
            for (int mt = 0; mt < 4; mt++)
                ldsm4(ahi[mt], smem_u32(&sAhi[(arow + mt * 16) * ASTR + acol]));
            {
                int brow = kk + (lane & 7) + ((lane >> 3) & 1) * 8;
                int bcol = wn * 16 + ((lane >> 4) << 3);
                ldsm4t(bh, smem_u32(&sBhi[brow * BSTR + bcol]));
            }
#pragma unroll
            for (int mt = 0; mt < 4; mt++)
#pragma unroll
                for (int nt = 0; nt < 2; nt++)
                    mma16816h(acc[mt][nt], ahi[mt], bh[nt * 2], bh[nt * 2 + 1]);
        }
        __syncthreads();
    }

    // ---- epilogue: bias, store fp16 ----
#pragma unroll
    for (int mt = 0; mt < 4; mt++)
#pragma unroll
        for (int nt = 0; nt < 2; nt++) {
            int cl = wn * 16 + nt * 8 + (lane & 3) * 2;
#pragma unroll
            for (int half = 0; half < 2; half++) {
                acc[mt][nt][half * 2 + 0] += sbias[cl + 0];
                acc[mt][nt][half * 2 + 1] += sbias[cl + 1];
            }
        }
#pragma unroll
    for (int mt = 0; mt < 4; mt++)
#pragma unroll
        for (int half = 0; half < 2; half++) {
            int gr = row0 + wm * 64 + mt * 16 + (lane >> 2) + half * 8;
            if (gr < M) {
#pragma unroll
                for (int nt = 0; nt < 2; nt++) {
                    int gc = col0 + wn * 16 + nt * 8 + (lane & 3) * 2;
                    *(__half2*)(C16 + (size_t)gr * 256 + gc) =
                        __floats2half2_rn(acc[mt][nt][half * 2 + 0],
                                          acc[mt][nt][half * 2 + 1]);
                }
            }
        }

    // ---- fused per-node dots (single pass: all 5 vectors, 2 barriers total) ----
    __syncthreads();
#pragma unroll
    for (int mt = 0; mt < 4; mt++)
#pragma unroll
        for (int half = 0; half < 2; half++) {
            float p[5];
#pragma unroll
            for (int v = 0; v < 5; v++) p[v] = 0.f;
#pragma unroll
            for (int nt = 0; nt < 2; nt++) {
                int cl = wn * 16 + nt * 8 + (lane & 3) * 2;
                float a0 = acc[mt][nt][half * 2 + 0];
                float a1 = acc[mt][nt][half * 2 + 1];
#pragma unroll
                for (int v = 0; v < 5; v++) {
                    if (!vp[v]) continue;
                    p[v] = fmaf(a0, sattn[v][cl + 0], p[v]);
                    p[v] = fmaf(a1, sattn[v][cl + 1], p[v]);
                }
            }
            int ridx = wm * 64 + mt * 16 + (lane >> 2) + half * 8;
#pragma unroll
            for (int v = 0; v < 5; v++) {
                if (!vp[v]) continue;
                float q = p[v];
                q += __shfl_xor_sync(0xffffffffu, q, 1);
                q += __shfl_xor_sync(0xffffffffu, q, 2);
                if ((lane & 3) == 0) spart[v][wn][ridx] = q;
            }
        }
    __syncthreads();
    {
        int row = tid >> 1, j = tid & 1;
        int gr = row0 + row;
        if (gr < M) {
#pragma unroll
            for (int v = 0; v < 5; v++) {
                if (!vp[v]) continue;
                op[v][(size_t)gr * 8 + blockIdx.y * 2 + j] =
                    spart[v][2 * j][row] + spart[v][2 * j + 1][row];
            }
        }
    }
}

// ---------------- counting sort by dst (3 relations) ----------------
__global__ __launch_bounds__(256)
void count3_kernel(const int* __restrict__ e0, const int* __restrict__ e1,
                   const int* __restrict__ e2, int* __restrict__ cnt) {
    int t = blockIdx.x * 256 + threadIdx.x;
    if (t >= EED) return;
    atomicAdd(&cnt[0 * NNA + __ldg(e0 + EED + t)], 1);
    atomicAdd(&cnt[1 * NNA + __ldg(e1 + EED + t)], 1);
    atomicAdd(&cnt[2 * NNA + __ldg(e2 + EED + t)], 1);
}

__global__ __launch_bounds__(256)
void scan_blocks(const int* __restrict__ cnt, int* __restrict__ rowptr,
                 int* __restrict__ blocksum) {
    int bx = blockIdx.x;           // 0..119
    int r = bx / 40, ch = bx % 40;
    const int4* c4 = (const int4*)(cnt + r * NNA + ch * 1000);
    int4* rp4 = (int4*)(rowptr + r * RPSTR + ch * 1000);
    int t = threadIdx.x, lane = t & 31, wid = t >> 5;

    int4 v = make_int4(0, 0, 0, 0);
    if (t < 250) v = c4[t];
    int ts = v.x + v.y + v.z + v.w;

    int inc = ts;
#pragma unroll
    for (int off = 1; off < 32; off <<= 1) {
        int u = __shfl_up_sync(0xffffffffu, inc, off);
        if (lane >= off) inc += u;
    }
    __shared__ int wsum[8];
    if (lane == 31) wsum[wid] = inc;
    __syncthreads();
    if (wid == 0) {
        int x = (lane < 8) ? wsum[lane] : 0;
#pragma unroll
        for (int off = 1; off < 8; off <<= 1) {
            int u = __shfl_up_sync(0xffffffffu, x, off);
            if (lane >= off) x += u;
        }
        if (lane < 8) wsum[lane] = x;
    }
    __syncthreads();
    int excl = ((wid == 0) ? 0 : wsum[wid - 1]) + inc - ts;
    if (t < 250) {
        int4 o;
        o.x = excl;
        o.y = excl + v.x;
        o.z = o.y + v.y;
        o.w = o.z + v.z;
        rp4[t] = o;
    }
    if (t == 0) blocksum[bx] = wsum[7];
}

__global__ __launch_bounds__(96)
void scan_top(int* __restrict__ blocksum, int* __restrict__ rowptr) {
    int r = threadIdx.x >> 5;
    int lane = threadIdx.x & 31;
    int* bs = blocksum + r * 40;
    int a = __ldg(bs + lane);
    int b = (lane < 8) ? __ldg(bs + 32 + lane) : 0;
    int ia = a, ib = b;
#pragma unroll
    for (int off = 1; off < 32; off <<= 1) {
        int u = __shfl_up_sync(0xffffffffu, ia, off);
        if (lane >= off) ia += u;
    }
#pragma unroll
    for (int off = 1; off < 8; off <<= 1) {
        int u = __shfl_up_sync(0xffffffffu, ib, off);
        if (lane >= off) ib += u;
    }
    int tot32 = __shfl_sync(0xffffffffu, ia, 31);
    int totb  = __shfl_sync(0xffffffffu, ib, 7);
    bs[lane] = ia - a;
    if (lane < 8) bs[32 + lane] = tot32 + ib - b;
    if (lane == 0) rowptr[r * RPSTR + NNA] = tot32 + totb;
}

__global__ __launch_bounds__(256)
void scan_add(int* __restrict__ rowptr, const int* __restrict__ blocksum,
              int* __restrict__ cnt) {
    int bx = blockIdx.x;
    int r = bx / 40, ch = bx % 40;
    int t = threadIdx.x;
    if (t >= 250) return;
    int off = __ldg(blocksum + bx);
    int4* rp4 = (int4*)(rowptr + r * RPSTR + ch * 1000);
    int4* cu4 = (int4*)(cnt + r * NNA + ch * 1000);
    int4 v = rp4[t];
    v.x += off; v.y += off; v.z += off; v.w += off;
    rp4[t] = v;
    cu4[t] = v;
}

__global__ __launch_bounds__(256)
void scatter3_kernel(const int* __restrict__ e0, const int* __restrict__ e1,
                     const int* __restrict__ e2,
                     int* __restrict__ cursor, int* __restrict__ srcs) {
    int t = blockIdx.x * 256 + threadIdx.x;
    if (t >= EED) return;
    {
        int dst = __ldg(e0 + EED + t);
        int pos = atomicAdd(&cursor[0 * NNA + dst], 1);
        srcs[0 * EED + pos] = __ldg(e0 + t);
    }
    {
        int dst = __ldg(e1 + EED + t);
        int pos = atomicAdd(&cursor[1 * NNA + dst], 1);
        srcs[1 * EED + pos] = __ldg(e1 + t);
    }
    {
        int dst = __ldg(e2 + EED + t);
        int pos = atomicAdd(&cursor[2 * NNA + dst], 1);
        srcs[2 * EED + pos] = __ldg(e2 + t);
    }
}

// ---------------- fused CSR aggregation + beta (warp = one (node,relation) walk) ---
__device__ __forceinline__ void accum8(float* acc, uint4 v, float ex) {
    __half2* h2 = (__half2*)&v;
#pragma unroll
    for (int j = 0; j < 4; j++) {
        float2 f = __half22float2(h2[j]);
        acc[2 * j + 0] = fmaf(ex, f.x, acc[2 * j + 0]);
        acc[2 * j + 1] = fmaf(ex, f.y, acc[2 * j + 1]);
    }
}

__device__ __forceinline__ void csr_walk(const int* __restrict__ srcs,
                                         int start, int end,
                                         const float* __restrict__ al,
                                         int head, float arh,
                                         const __half* __restrict__ hs,
                                         int lane, float* acc, float& den) {
    for (int base = start; base < end; base += 32) {
        int n = min(32, end - base);
        int mysrc = (base + lane < end) ? __ldg(srcs + base + lane) : 0;
        int i = 0;
        for (; i + 4 <= n; i += 4) {
            int s0 = __shfl_sync(0xffffffffu, mysrc, i);
            int s1 = __shfl_sync(0xffffffffu, mysrc, i + 1);
            int s2 = __shfl_sync(0xffffffffu, mysrc, i + 2);
            int s3 = __shfl_sync(0xffffffffu, mysrc, i + 3);
            uint4 v0 = __ldg((const uint4*)(hs + (size_t)s0 * 256) + lane);
            uint4 v1 = __ldg((const uint4*)(hs + (size_t)s1 * 256) + lane);
            uint4 v2 = __ldg((const uint4*)(hs + (size_t)s2 * 256) + lane);
            uint4 v3 = __ldg((const uint4*)(hs + (size_t)s3 * 256) + lane);
            float ex0 = __expf(leaky02(__ldg(al + s0 * 8 + head) + arh));
            float ex1 = __expf(leaky02(__ldg(al + s1 * 8 + head) + arh));
            float ex2 = __expf(leaky02(__ldg(al + s2 * 8 + head) + arh));
            float ex3 = __expf(leaky02(__ldg(al + s3 * 8 + head) + arh));
            den += (ex0 + ex1) + (ex2 + ex3);
            accum8(acc, v0, ex0);
            accum8(acc, v1, ex1);
            accum8(acc, v2, ex2);
            accum8(acc, v3, ex3);
        }
        for (; i < n; i++) {
            int s0 = __shfl_sync(0xffffffffu, mysrc, i);
            uint4 v0 = __ldg((const uint4*)(hs + (size_t)s0 * 256) + lane);
            float ex0 = __expf(leaky02(__ldg(al + s0 * 8 + head) + arh));
            den += ex0;
            accum8(acc, v0, ex0);
        }
    }
}

__device__ __forceinline__ float quad_sum(float p) {
    p += __shfl_xor_sync(0xffffffffu, p, 1);
    p += __shfl_xor_sync(0xffffffffu, p, 2);
    return p;
}

__device__ __forceinline__ void load8f(const __half* hp, int lane, float* xs) {
    uint4 u = __ldg((const uint4*)hp + lane);
    __half2* h2 = (__half2*)&u;
#pragma unroll
    for (int j = 0; j < 4; j++) {
        float2 f = __half22float2(h2[j]);
        xs[2 * j + 0] = f.x;
        xs[2 * j + 1] = f.y;
    }
}

#define NA_BLK (NNA / 4)   // 10000 A-blocks: 4 nodes x 2 relation-warps
#define NB_BLK (NNB / 8)   // 5000 B-blocks: 8 nodes

__global__ __launch_bounds__(256)
void aggbeta_all(const int* __restrict__ srcs_all, const int* __restrict__ rowptr,
                 const float* __restrict__ al1, const float* __restrict__ ar1,
                 const float* __restrict__ al2, const float* __restrict__ ar2,
                 const float* __restrict__ al0, const float* __restrict__ ar0,
                 const __half* __restrict__ hA16, const __half* __restrict__ hB16,
                 const float* __restrict__ blA, const float* __restrict__ blB,
                 const float* __restrict__ rel_r_A, const float* __restrict__ rel_r_B,
                 float* __restrict__ out) {
    __shared__ float sacc[4][8][32];   // odd (AA) warps publish normalized acc
    int wid = threadIdx.x >> 5;
    int lane = threadIdx.x & 31;
    int head = lane >> 2;

    if (blockIdx.x < NA_BLK) {
        int node = blockIdx.x * 4 + (wid >> 1);
        int rel  = wid & 1;   // 0 = BA (gather hB16), 1 = AA (gather hA16)

        float acc[8];
#pragma unroll
        for (int j = 0; j < 8; j++) acc[j] = 0.f;
        float den = 0.f;
        if (rel == 0) {
            int s = __ldg(rowptr + 0 * RPSTR + node), e = __ldg(rowptr + 0 * RPSTR + node + 1);
            csr_walk(srcs_all + 0 * EED, s, e, al1, head,
                     __ldg(ar1 + node * 8 + head), hB16, lane, acc, den);
        } else {
            int s = __ldg(rowptr + 1 * RPSTR + node), e = __ldg(rowptr + 1 * RPSTR + node + 1);
            csr_walk(srcs_all + 1 * EED, s, e, al2, head,
                     __ldg(ar2 + node * 8 + head), hA16, lane, acc, den);
        }
        float inv = den > 0.f ? 1.f / den : 0.f;
#pragma unroll
        for (int j = 0; j < 8; j++) acc[j] *= inv;

        if (rel == 1) {
#pragma unroll
            for (int j = 0; j < 8; j++) sacc[wid >> 1][j][lane] = acc[j];
        }
        __syncthreads();
        if (rel == 0) {
            float acc1[8];
#pragma unroll
            for (int j = 0; j < 8; j++) acc1[j] = sacc[wid >> 1][j][lane];

            float xs[8], rs[8];
            load8f(hA16 + (size_t)node * 256, lane, xs);
            {
                float4 r0 = __ldg((const float4*)rel_r_A + lane * 2);
                float4 r1 = __ldg((const float4*)rel_r_A + lane * 2 + 1);
                rs[0] = r0.x; rs[1] = r0.y; rs[2] = r0.z; rs[3] = r0.w;
                rs[4] = r1.x; rs[5] = r1.y; rs[6] = r1.z; rs[7] = r1.w;
            }
            float p0 = 0.f, p1 = 0.f, p2 = 0.f;
#pragma unroll
            for (int j = 0; j < 8; j++) {
                p0 = fmaf(acc[j],  rs[j], p0);
                p1 = fmaf(acc1[j], rs[j], p1);
                p2 = fmaf(xs[j],   rs[j], p2);
            }
            float b0 = quad_sum(p0), b1 = quad_sum(p1), b2 = quad_sum(p2);
            float bl = __ldg(blA + node * 8 + head);

            float s0 = leaky02(bl + b0);
            float s1 = leaky02(bl + b1);
            float s2 = leaky02(bl + b2);
            float mx = fmaxf(s0, fmaxf(s1, s2));
            float w0 = __expf(s0 - mx), w1 = __expf(s1 - mx), w2 = __expf(s2 - mx);
            float inv3 = 1.f / (w0 + w1 + w2);

            float o[8];
#pragma unroll
            for (int j = 0; j < 8; j++)
                o[j] = fmaxf((acc[j] * w0 + acc1[j] * w1 + xs[j] * w2) * inv3, 0.f);
            float4* op = (float4*)(out + (size_t)node * 256);
            op[lane * 2]     = make_float4(o[0], o[1], o[2], o[3]);
            op[lane * 2 + 1] = make_float4(o[4], o[5], o[6], o[7]);
        }
    } else {
        int node = (blockIdx.x - NA_BLK) * 8 + wid;
        float acc[8];
#pragma unroll
        for (int j = 0; j < 8; j++) acc[j] = 0.f;
        float den = 0.f;
        {
            int s = __ldg(rowptr + 2 * RPSTR + node), e = __ldg(rowptr + 2 * RPSTR + node + 1);
            csr_walk(srcs_all + 2 * EED, s, e, al0, head,
                     __ldg(ar0 + node * 8 + head), hA16, lane, acc, den);
        }
        float inv = den > 0.f ? 1.f / den : 0.f;
#pragma unroll
        for (int j = 0; j < 8; j++) acc[j] *= inv;

        float xs[8], rs[8];
        load8f(hB16 + (size_t)node * 256, lane, xs);
        {
            float4 r0 = __ldg((const float4*)rel_r_B + lane * 2);
            float4 r1 = __ldg((const float4*)rel_r_B + lane * 2 + 1);
            rs[0] = r0.x; rs[1] = r0.y; rs[2] = r0.z; rs[3] = r0.w;
            rs[4] = r1.x; rs[5] = r1.y; rs[6] = r1.z; rs[7] = r1.w;
        }
        float p0 = 0.f, p1 = 0.f;
#pragma unroll
        for (int j = 0; j < 8; j++) {
            p0 = fmaf(acc[j], rs[j], p0);
            p1 = fmaf(xs[j],  rs[j], p1);
        }
        float b0 = quad_sum(p0), b1 = quad_sum(p1);
        float bl = __ldg(blB + node * 8 + head);

        float s0 = leaky02(bl + b0);
        float s1 = leaky02(bl + b1);
        float mx = fmaxf(s0, s1);
        float w0 = __expf(s0 - mx), w1 = __expf(s1 - mx);
        float inv2 = 1.f / (w0 + w1);

        float o[8];
#pragma unroll
        for (int j = 0; j < 8; j++)
            o[j] = fmaxf((acc[j] * w0 + xs[j] * w1) * inv2, 0.f);
        float4* op = (float4*)(out + (size_t)(NNA + node) * 256);
        op[lane * 2]     = make_float4(o[0], o[1], o[2], o[3]);
        op[lane * 2 + 1] = make_float4(o[4], o[5], o[6], o[7]);
    }
}

// ---------------- launch ----------------
extern "C" void kernel_launch(void* const* d_in, const int* in_sizes, int n_in,
                              void* d_out, int out_size) {
    const float* x_A     = (const float*)d_in[0];
    const float* x_B     = (const float*)d_in[1];
    const int*   e_ab    = (const int*)d_in[2];
    const int*   e_ba    = (const int*)d_in[3];
    const int*   e_aa    = (const int*)d_in[4];
    const float* W_A     = (const float*)d_in[5];
    const float* b_A     = (const float*)d_in[6];
    const float* W_B     = (const float*)d_in[7];
    const float* b_B     = (const float*)d_in[8];
    const float* attn_l  = (const float*)d_in[9];   // [3,8,32]
    const float* attn_r  = (const float*)d_in[10];
    const float* rel_l_A = (const float*)d_in[11];
    const float* rel_r_A = (const float*)d_in[12];
    const float* rel_l_B = (const float*)d_in[13];
    const float* rel_r_B = (const float*)d_in[14];
    float* out = (float*)d_out;

    void *p_hA16, *p_hB16, *p_W16;
    void *p_al0, *p_ar0, *p_al1, *p_ar1, *p_al2, *p_ar2, *p_blA, *p_blB;
    void *p_srcs, *p_cnt, *p_rowptr, *p_bsum;
    cudaGetSymbolAddress(&p_hA16, g_hA16);
    cudaGetSymbolAddress(&p_hB16, g_hB16);
    cudaGetSymbolAddress(&p_W16, g_W16);
    cudaGetSymbolAddress(&p_al0, g_al0);
    cudaGetSymbolAddress(&p_ar0, g_ar0);
    cudaGetSymbolAddress(&p_al1, g_al1);
    cudaGetSymbolAddress(&p_ar1, g_ar1);
    cudaGetSymbolAddress(&p_al2, g_al2);
    cudaGetSymbolAddress(&p_ar2, g_ar2);
    cudaGetSymbolAddress(&p_blA, g_blA);
    cudaGetSymbolAddress(&p_blB, g_blB);
    cudaGetSymbolAddress(&p_srcs, g_srcs);
    cudaGetSymbolAddress(&p_cnt, g_cnt);
    cudaGetSymbolAddress(&p_rowptr, g_rowptr);
    cudaGetSymbolAddress(&p_bsum, g_blocksum);

    int* cnt    = (int*)p_cnt;
    int* rowptr = (int*)p_rowptr;
    int* srcs   = (int*)p_srcs;
    int* bsum   = (int*)p_bsum;

    // one-time infra (no device memory allocation)
    static cudaStream_t s1 = nullptr;
    static cudaEvent_t evFork = nullptr, evJoin = nullptr;
    if (!s1) {
        cudaStreamCreateWithFlags(&s1, cudaStreamNonBlocking);
        cudaEventCreateWithFlags(&evFork, cudaEventDisableTiming);
        cudaEventCreateWithFlags(&evJoin, cudaEventDisableTiming);
    }

    // fork: sort chain on s1 runs concurrently with wsplit+GEMM on stream 0
    cudaEventRecord(evFork, 0);
    cudaStreamWaitEvent(s1, evFork, 0);
    {
        cudaMemsetAsync(cnt, 0, sizeof(int) * 3 * NNA, s1);
        int g = (EED + 255) / 256;
        count3_kernel<<<g, 256, 0, s1>>>(e_ba, e_aa, e_ab, cnt);
        scan_blocks<<<120, 256, 0, s1>>>(cnt, rowptr, bsum);
        scan_top<<<1, 96, 0, s1>>>(bsum, rowptr);
        scan_add<<<120, 256, 0, s1>>>(rowptr, bsum, cnt);
        scatter3_kernel<<<g, 256, 0, s1>>>(e_ba, e_aa, e_ab, cnt, srcs);
        cudaEventRecord(evJoin, s1);
    }

    // stream 0: W fp16 convert then merged projections (plain fp16 mma)
    {
        dim3 gw(64, 2);
        wsplit_kernel<<<gw, 256>>>(W_A, W_B, (__half*)p_W16);
        dim3 grid((NNA + 127) / 128, 4, 2);
        gemm_fused2<<<grid, 256>>>(x_A, x_B,
                                   (const __half*)p_W16,
                                   b_A, b_B,
                                   (__half*)p_hA16, (__half*)p_hB16,
                                   attn_l, attn_r, rel_l_A, rel_l_B,
                                   (float*)p_al0, (float*)p_ar1,
                                   (float*)p_al2, (float*)p_ar2, (float*)p_blA,
                                   (float*)p_ar0, (float*)p_al1, (float*)p_blB);
    }

    // join: aggbeta needs both the GEMM outputs and the CSR
    cudaStreamWaitEvent(0, evJoin, 0);
    aggbeta_all<<<NA_BLK + NB_BLK, 256>>>(srcs, rowptr,
                                          (float*)p_al1, (float*)p_ar1,
                                          (float*)p_al2, (float*)p_ar2,
                                          (float*)p_al0, (float*)p_ar0,
                                          (const __half*)p_hA16,
                                          (const __half*)p_hB16,
                                          (float*)p_blA, (float*)p_blB,
                                          rel_r_A, rel_r_B, out);

    (void)in_sizes; (void)n_in; (void)out_size;
}

// round 16
// speedup vs baseline: 1.4626x; 1.4626x over previous
#include <cuda_runtime.h>
#include <cuda_bf16.h>
#include <cuda_fp16.h>
#include <math.h>
#include <stdint.h>

// Problem constants (fixed shapes per reference)
#define NNA 40000
#define NNB 40000
#define EED 400000
#define DD  256
#define HH  8
#define RPSTR 40004   // rowptr per-relation stride

// ---------------- scratch (static device globals; no allocation) ----------------
__device__ __half g_hA16[NNA * DD];
__device__ __half g_hB16[NNB * DD];
__device__ __half g_W16[2 * 65536];   // W fp16, [side][k][n]
__device__ float  g_al0[NNA * HH];
__device__ float  g_ar0[NNB * HH];
__device__ float  g_al1[NNB * HH];
__device__ float  g_ar1[NNA * HH];
__device__ float  g_al2[NNA * HH];
__device__ float  g_ar2[NNA * HH];
__device__ float  g_blA[NNA * HH];
__device__ float  g_blB[NNB * HH];
__device__ int    g_srcs[3 * EED];
__device__ int    g_cnt[3 * NNA];
__device__ int    g_rowptr[3 * RPSTR];
__device__ int    g_blocksum[128];

// ---------------- helpers ----------------
__device__ __forceinline__ float leaky02(float x) { return x > 0.f ? x : 0.2f * x; }

__device__ __forceinline__ uint32_t smem_u32(const void* p) {
    uint32_t a;
    asm("{ .reg .u64 t; cvta.to.shared.u64 t, %1; cvt.u32.u64 %0, t; }" : "=r"(a) : "l"(p));
    return a;
}
__device__ __forceinline__ void ldsm4(uint32_t* r, uint32_t a) {
    asm volatile("ldmatrix.sync.aligned.m8n8.x4.shared.b16 {%0,%1,%2,%3}, [%4];"
                 : "=r"(r[0]), "=r"(r[1]), "=r"(r[2]), "=r"(r[3]) : "r"(a));
}
__device__ __forceinline__ void ldsm4t(uint32_t* r, uint32_t a) {
    asm volatile("ldmatrix.sync.aligned.m8n8.x4.trans.shared.b16 {%0,%1,%2,%3}, [%4];"
                 : "=r"(r[0]), "=r"(r[1]), "=r"(r[2]), "=r"(r[3]) : "r"(a));
}
// fp16 x fp16 -> fp32 accumulate
__device__ __forceinline__ void mma16816h(float* d, const uint32_t* a, uint32_t b0, uint32_t b1) {
    asm volatile("mma.sync.aligned.m16n8k16.row.col.f32.f16.f16.f32 "
                 "{%0,%1,%2,%3}, {%4,%5,%6,%7}, {%8,%9}, {%0,%1,%2,%3};"
                 : "+f"(d[0]), "+f"(d[1]), "+f"(d[2]), "+f"(d[3])
                 : "r"(a[0]), "r"(a[1]), "r"(a[2]), "r"(a[3]), "r"(b0), "r"(b1));
}

// ---------------- W fp16 convert (runs once, tiny) ----------------
__global__ __launch_bounds__(256)
void wsplit_kernel(const float* __restrict__ WA, const float* __restrict__ WB,
                   __half* __restrict__ W16) {
    const float* W = blockIdx.y ? WB : WA;
    __half* o = W16 + blockIdx.y * 65536;
    int i = (blockIdx.x * 256 + threadIdx.x) * 4;   // grid.x = 64
    float4 v = __ldg((const float4*)(W + i));
    __half2 h01 = __floats2half2_rn(v.x, v.y);
    __half2 h23 = __floats2half2_rn(v.z, v.w);
    *(uint2*)(o + i) = make_uint2(*(uint32_t*)&h01, *(uint32_t*)&h23);
}

// ---------------- merged GEMM (A and B sides via blockIdx.z) -----------------------
// plain fp16 mma: acc += ah*bh (both fp16-rounded); fp32 accumulate
#define ASTR 40
#define BSTR 72
__global__ __launch_bounds__(256)
void gemm_fused2(const float* __restrict__ xA, const float* __restrict__ xB,
                 const __half* __restrict__ W16,
                 const float* __restrict__ bA_, const float* __restrict__ bB_,
                 __half* __restrict__ hA16, __half* __restrict__ hB16,
                 const float* __restrict__ attn_l, const float* __restrict__ attn_r,
                 const float* __restrict__ rel_l_A, const float* __restrict__ rel_l_B,
                 float* __restrict__ al0, float* __restrict__ ar1,
                 float* __restrict__ al2, float* __restrict__ ar2,
                 float* __restrict__ blA,
                 float* __restrict__ ar0, float* __restrict__ al1,
                 float* __restrict__ blB) {
    __shared__ __half sAhi[128 * ASTR];
    __shared__ __half sBhi[32 * BSTR];
    __shared__ float sattn[5][64];
    __shared__ float sbias[64];
    __shared__ float spart[4][128];

    const int tid  = threadIdx.x;
    const int lane = tid & 31;
    const int wid  = tid >> 5;
    const int wm   = wid & 1;
    const int wn   = wid >> 1;
    const int row0 = blockIdx.x * 128;
    const int col0 = blockIdx.y * 64;
    const int M = NNA;

    const float* A; const float* bias; __half* C16;
    const __half* Bh;
    const float* vp[5]; float* op[5];
    if (blockIdx.z == 0) {
        A = xA; bias = bA_; C16 = hA16;
        Bh = W16;
        vp[0] = attn_l + 0;   op[0] = al0;
        vp[1] = attn_r + 256; op[1] = ar1;
        vp[2] = attn_l + 512; op[2] = al2;
        vp[3] = attn_r + 512; op[3] = ar2;
        vp[4] = rel_l_A;      op[4] = blA;
    } else {
        A = xB; bias = bB_; C16 = hB16;
        Bh = W16 + 65536;
        vp[0] = attn_r + 0;   op[0] = ar0;
        vp[1] = attn_l + 256; op[1] = al1;
        vp[2] = 0;            op[2] = 0;
        vp[3] = 0;            op[3] = 0;
        vp[4] = rel_l_B;      op[4] = blB;
    }

    if (tid < 64) sbias[tid] = __ldg(bias + col0 + tid);
#pragma unroll
    for (int v = 0; v < 5; v++)
        if (vp[v] && tid < 64) sattn[v][tid] = __ldg(vp[v] + col0 + tid);

    float acc[4][2][4];
#pragma unroll
    for (int i = 0; i < 4; i++)
#pragma unroll
        for (int j = 0; j < 2; j++)
#pragma unroll
            for (int k = 0; k < 4; k++) acc[i][j][k] = 0.f;

    float4 av[4];
    uint2 bvh[2];
#pragma unroll
    for (int p = 0; p < 4; p++) {
        int f = tid + 256 * p, r = f >> 3, c = (f & 7) * 4;
        int gr = row0 + r;
        av[p] = (gr < M) ? __ldg((const float4*)(A + (size_t)gr * 256 + c))
                         : make_float4(0.f, 0.f, 0.f, 0.f);
    }
#pragma unroll
    for (int p = 0; p < 2; p++) {
        int f = tid + 256 * p, r = f >> 4, c = (f & 15) * 4;
        bvh[p] = __ldg((const uint2*)(Bh + (size_t)r * 256 + col0 + c));
    }

    for (int kb = 0; kb < 8; kb++) {
#pragma unroll
        for (int p = 0; p < 4; p++) {
            int f = tid + 256 * p, r = f >> 3, c = (f & 7) * 4;
            __half2 h01 = __floats2half2_rn(av[p].x, av[p].y);
            __half2 h23 = __floats2half2_rn(av[p].z, av[p].w);
            *(uint2*)&sAhi[r * ASTR + c] = make_uint2(*(uint32_t*)&h01, *(uint32_t*)&h23);
        }
#pragma unroll
        for (int p = 0; p < 2; p++) {
            int f = tid + 256 * p, r = f >> 4, c = (f & 15) * 4;
            *(uint2*)&sBhi[r * BSTR + c] = bvh[p];
        }
        __syncthreads();

        if (kb < 7) {
            int k0 = (kb + 1) * 32;
#pragma unroll
            for (int p = 0; p < 4; p++) {
                int f = tid + 256 * p, r = f >> 3, c = (f & 7) * 4;
                int gr = row0 + r;
                av[p] = (gr < M) ? __ldg((const float4*)(A + (size_t)gr * 256 + k0 + c))
                                 : make_float4(0.f, 0.f, 0.f, 0.f);
            }
#pragma unroll
            for (int p = 0; p < 2; p++) {
                int f = tid + 256 * p, r = f >> 4, c = (f & 15) * 4;
                bvh[p] = __ldg((const uint2*)(Bh + (size_t)(k0 + r) * 256 + col0 + c));
            }
        }

#pragma unroll
        for (int kk = 0; kk < 32; kk += 16) {
            uint32_t ahi[4][4], bh[4];
            int arow = wm * 64 + (lane & 15);
            int acol = kk + ((lane >> 4) << 3);
#pragma unroll
            for (int mt = 0; mt < 4; mt++)
                ldsm4(ahi[mt], smem_u32(&sAhi[(arow + mt * 16) * ASTR + acol]));
            {
                int brow = kk + (lane & 7) + ((lane >> 3) & 1) * 8;
                int bcol = wn * 16 + ((lane >> 4) << 3);
                ldsm4t(bh, smem_u32(&sBhi[brow * BSTR + bcol]));
            }
#pragma unroll
            for (int mt = 0; mt < 4; mt++)
#pragma unroll
                for (int nt = 0; nt < 2; nt++)
                    mma16816h(acc[mt][nt], ahi[mt], bh[nt * 2], bh[nt * 2 + 1]);
        }
        __syncthreads();
    }

    // ---- epilogue: bias, store fp16 ----
#pragma unroll
    for (int mt = 0; mt < 4; mt++)
#pragma unroll
        for (int nt = 0; nt < 2; nt++) {
            int cl = wn * 16 + nt * 8 + (lane & 3) * 2;
#pragma unroll
            for (int half = 0; half < 2; half++) {
                acc[mt][nt][half * 2 + 0] += sbias[cl + 0];
                acc[mt][nt][half * 2 + 1] += sbias[cl + 1];
            }
        }
#pragma unroll
    for (int mt = 0; mt < 4; mt++)
#pragma unroll
        for (int half = 0; half < 2; half++) {
            int gr = row0 + wm * 64 + mt * 16 + (lane >> 2) + half * 8;
            if (gr < M) {
#pragma unroll
                for (int nt = 0; nt < 2; nt++) {
                    int gc = col0 + wn * 16 + nt * 8 + (lane & 3) * 2;
                    *(__half2*)(C16 + (size_t)gr * 256 + gc) =
                        __floats2half2_rn(acc[mt][nt][half * 2 + 0],
                                          acc[mt][nt][half * 2 + 1]);
                }
            }
        }

    // ---- fused per-node dots ----
#pragma unroll
    for (int v = 0; v < 5; v++) {
        if (!vp[v]) continue;
        __syncthreads();
#pragma unroll
        for (int mt = 0; mt < 4; mt++)
#pragma unroll
            for (int half = 0; half < 2; half++) {
                float p = 0.f;
#pragma unroll
                for (int nt = 0; nt < 2; nt++) {
                    int cl = wn * 16 + nt * 8 + (lane & 3) * 2;
                    p = fmaf(acc[mt][nt][half * 2 + 0], sattn[v][cl + 0], p);
                    p = fmaf(acc[mt][nt][half * 2 + 1], sattn[v][cl + 1], p);
                }
                p += __shfl_xor_sync(0xffffffffu, p, 1);
                p += __shfl_xor_sync(0xffffffffu, p, 2);
                if ((lane & 3) == 0)
                    spart[wn][wm * 64 + mt * 16 + (lane >> 2) + half * 8] = p;
            }
        __syncthreads();
        {
            int row = tid >> 1, j = tid & 1;
            int gr = row0 + row;
            if (gr < M)
                op[v][(size_t)gr * 8 + blockIdx.y * 2 + j] =
                    spart[2 * j][row] + spart[2 * j + 1][row];
        }
    }
}

// ---------------- counting sort by dst (3 relations) ----------------
__global__ __launch_bounds__(256)
void count3_kernel(const int* __restrict__ e0, const int* __restrict__ e1,
                   const int* __restrict__ e2, int* __restrict__ cnt) {
    int t = blockIdx.x * 256 + threadIdx.x;
    if (t >= EED) return;
    atomicAdd(&cnt[0 * NNA + __ldg(e0 + EED + t)], 1);
    atomicAdd(&cnt[1 * NNA + __ldg(e1 + EED + t)], 1);
    atomicAdd(&cnt[2 * NNA + __ldg(e2 + EED + t)], 1);
}

__global__ __launch_bounds__(256)
void scan_blocks(const int* __restrict__ cnt, int* __restrict__ rowptr,
                 int* __restrict__ blocksum) {
    int bx = blockIdx.x;           // 0..119
    int r = bx / 40, ch = bx % 40;
    const int4* c4 = (const int4*)(cnt + r * NNA + ch * 1000);
    int4* rp4 = (int4*)(rowptr + r * RPSTR + ch * 1000);
    int t = threadIdx.x, lane = t & 31, wid = t >> 5;

    int4 v = make_int4(0, 0, 0, 0);
    if (t < 250) v = c4[t];
    int ts = v.x + v.y + v.z + v.w;

    int inc = ts;
#pragma unroll
    for (int off = 1; off < 32; off <<= 1) {
        int u = __shfl_up_sync(0xffffffffu, inc, off);
        if (lane >= off) inc += u;
    }
    __shared__ int wsum[8];
    if (lane == 31) wsum[wid] = inc;
    __syncthreads();
    if (wid == 0) {
        int x = (lane < 8) ? wsum[lane] : 0;
#pragma unroll
        for (int off = 1; off < 8; off <<= 1) {
            int u = __shfl_up_sync(0xffffffffu, x, off);
            if (lane >= off) x += u;
        }
        if (lane < 8) wsum[lane] = x;
    }
    __syncthreads();
    int excl = ((wid == 0) ? 0 : wsum[wid - 1]) + inc - ts;
    if (t < 250) {
        int4 o;
        o.x = excl;
        o.y = excl + v.x;
        o.z = o.y + v.y;
        o.w = o.z + v.z;
        rp4[t] = o;
    }
    if (t == 0) blocksum[bx] = wsum[7];
}

__global__ __launch_bounds__(96)
void scan_top(int* __restrict__ blocksum, int* __restrict__ rowptr) {
    int r = threadIdx.x >> 5;
    int lane = threadIdx.x & 31;
    int* bs = blocksum + r * 40;
    int a = __ldg(bs + lane);
    int b = (lane < 8) ? __ldg(bs + 32 + lane) : 0;
    int ia = a, ib = b;
#pragma unroll
    for (int off = 1; off < 32; off <<= 1) {
        int u = __shfl_up_sync(0xffffffffu, ia, off);
        if (lane >= off) ia += u;
    }
#pragma unroll
    for (int off = 1; off < 8; off <<= 1) {
        int u = __shfl_up_sync(0xffffffffu, ib, off);
        if (lane >= off) ib += u;
    }
    int tot32 = __shfl_sync(0xffffffffu, ia, 31);
    int totb  = __shfl_sync(0xffffffffu, ib, 7);
    bs[lane] = ia - a;
    if (lane < 8) bs[32 + lane] = tot32 + ib - b;
    if (lane == 0) rowptr[r * RPSTR + NNA] = tot32 + totb;
}

__global__ __launch_bounds__(256)
void scan_add(int* __restrict__ rowptr, const int* __restrict__ blocksum,
              int* __restrict__ cnt) {
    int bx = blockIdx.x;
    int r = bx / 40, ch = bx % 40;
    int t = threadIdx.x;
    if (t >= 250) return;
    int off = __ldg(blocksum + bx);
    int4* rp4 = (int4*)(rowptr + r * RPSTR + ch * 1000);
    int4* cu4 = (int4*)(cnt + r * NNA + ch * 1000);
    int4 v = rp4[t];
    v.x += off; v.y += off; v.z += off; v.w += off;
    rp4[t] = v;
    cu4[t] = v;
}

__global__ __launch_bounds__(256)
void scatter3_kernel(const int* __restrict__ e0, const int* __restrict__ e1,
                     const int* __restrict__ e2,
                     int* __restrict__ cursor, int* __restrict__ srcs) {
    int t = blockIdx.x * 256 + threadIdx.x;
    if (t >= EED) return;
    {
        int dst = __ldg(e0 + EED + t);
        int pos = atomicAdd(&cursor[0 * NNA + dst], 1);
        srcs[0 * EED + pos] = __ldg(e0 + t);
    }
    {
        int dst = __ldg(e1 + EED + t);
        int pos = atomicAdd(&cursor[1 * NNA + dst], 1);
        srcs[1 * EED + pos] = __ldg(e1 + t);
    }
    {
        int dst = __ldg(e2 + EED + t);
        int pos = atomicAdd(&cursor[2 * NNA + dst], 1);
        srcs[2 * EED + pos] = __ldg(e2 + t);
    }
}

// ---------------- fused CSR aggregation + beta (warp = one (node,relation) walk) ---
__device__ __forceinline__ void accum8(float* acc, uint4 v, float ex) {
    __half2* h2 = (__half2*)&v;
#pragma unroll
    for (int j = 0; j < 4; j++) {
        float2 f = __half22float2(h2[j]);
        acc[2 * j + 0] = fmaf(ex, f.x, acc[2 * j + 0]);
        acc[2 * j + 1] = fmaf(ex, f.y, acc[2 * j + 1]);
    }
}

__device__ __forceinline__ void csr_walk(const int* __restrict__ srcs,
                                         int start, int end,
                                         const float* __restrict__ al,
                                         int head, float arh,
                                         const __half* __restrict__ hs,
                                         int lane, float* acc, float& den) {
    for (int base = start; base < end; base += 32) {
        int n = min(32, end - base);
        int mysrc = (base + lane < end) ? __ldg(srcs + base + lane) : 0;
        int i = 0;
        for (; i + 4 <= n; i += 4) {
            int s0 = __shfl_sync(0xffffffffu, mysrc, i);
            int s1 = __shfl_sync(0xffffffffu, mysrc, i + 1);
            int s2 = __shfl_sync(0xffffffffu, mysrc, i + 2);
            int s3 = __shfl_sync(0xffffffffu, mysrc, i + 3);
            uint4 v0 = __ldg((const uint4*)(hs + (size_t)s0 * 256) + lane);
            uint4 v1 = __ldg((const uint4*)(hs + (size_t)s1 * 256) + lane);
            uint4 v2 = __ldg((const uint4*)(hs + (size_t)s2 * 256) + lane);
            uint4 v3 = __ldg((const uint4*)(hs + (size_t)s3 * 256) + lane);
            float ex0 = __expf(leaky02(__ldg(al + s0 * 8 + head) + arh));
            float ex1 = __expf(leaky02(__ldg(al + s1 * 8 + head) + arh));
            float ex2 = __expf(leaky02(__ldg(al + s2 * 8 + head) + arh));
            float ex3 = __expf(leaky02(__ldg(al + s3 * 8 + head) + arh));
            den += (ex0 + ex1) + (ex2 + ex3);
            accum8(acc, v0, ex0);
            accum8(acc, v1, ex1);
            accum8(acc, v2, ex2);
            accum8(acc, v3, ex3);
        }
        for (; i < n; i++) {
            int s0 = __shfl_sync(0xffffffffu, mysrc, i);
            uint4 v0 = __ldg((const uint4*)(hs + (size_t)s0 * 256) + lane);
            float ex0 = __expf(leaky02(__ldg(al + s0 * 8 + head) + arh));
            den += ex0;
            accum8(acc, v0, ex0);
        }
    }
}

__device__ __forceinline__ float quad_sum(float p) {
    p += __shfl_xor_sync(0xffffffffu, p, 1);
    p += __shfl_xor_sync(0xffffffffu, p, 2);
    return p;
}

__device__ __forceinline__ void load8f(const __half* hp, int lane, float* xs) {
    uint4 u = __ldg((const uint4*)hp + lane);
    __half2* h2 = (__half2*)&u;
#pragma unroll
    for (int j = 0; j < 4; j++) {
        float2 f = __half22float2(h2[j]);
        xs[2 * j + 0] = f.x;
        xs[2 * j + 1] = f.y;
    }
}

#define NA_BLK (NNA / 4)   // 10000 A-blocks: 4 nodes x 2 relation-warps
#define NB_BLK (NNB / 8)   // 5000 B-blocks: 8 nodes

__global__ __launch_bounds__(256)
void aggbeta_all(const int* __restrict__ srcs_all, const int* __restrict__ rowptr,
                 const float* __restrict__ al1, const float* __restrict__ ar1,
                 const float* __restrict__ al2, const float* __restrict__ ar2,
                 const float* __restrict__ al0, const float* __restrict__ ar0,
                 const __half* __restrict__ hA16, const __half* __restrict__ hB16,
                 const float* __restrict__ blA, const float* __restrict__ blB,
                 const float* __restrict__ rel_r_A, const float* __restrict__ rel_r_B,
                 float* __restrict__ out) {
    __shared__ float sacc[4][8][32];   // odd (AA) warps publish normalized acc
    int wid = threadIdx.x >> 5;
    int lane = threadIdx.x & 31;
    int head = lane >> 2;

    if (blockIdx.x < NA_BLK) {
        int node = blockIdx.x * 4 + (wid >> 1);
        int rel  = wid & 1;   // 0 = BA (gather hB16), 1 = AA (gather hA16)

        float acc[8];
#pragma unroll
        for (int j = 0; j < 8; j++) acc[j] = 0.f;
        float den = 0.f;
        if (rel == 0) {
            int s = __ldg(rowptr + 0 * RPSTR + node), e = __ldg(rowptr + 0 * RPSTR + node + 1);
            csr_walk(srcs_all + 0 * EED, s, e, al1, head,
                     __ldg(ar1 + node * 8 + head), hB16, lane, acc, den);
        } else {
            int s = __ldg(rowptr + 1 * RPSTR + node), e = __ldg(rowptr + 1 * RPSTR + node + 1);
            csr_walk(srcs_all + 1 * EED, s, e, al2, head,
                     __ldg(ar2 + node * 8 + head), hA16, lane, acc, den);
        }
        float inv = den > 0.f ? 1.f / den : 0.f;
#pragma unroll
        for (int j = 0; j < 8; j++) acc[j] *= inv;

        if (rel == 1) {
#pragma unroll
            for (int j = 0; j < 8; j++) sacc[wid >> 1][j][lane] = acc[j];
        }
        __syncthreads();
        if (rel == 0) {
            float acc1[8];
#pragma unroll
            for (int j = 0; j < 8; j++) acc1[j] = sacc[wid >> 1][j][lane];

            float xs[8], rs[8];
            load8f(hA16 + (size_t)node * 256, lane, xs);
            {
                float4 r0 = __ldg((const float4*)rel_r_A + lane * 2);
                float4 r1 = __ldg((const float4*)rel_r_A + lane * 2 + 1);
                rs[0] = r0.x; rs[1] = r0.y; rs[2] = r0.z; rs[3] = r0.w;
                rs[4] = r1.x; rs[5] = r1.y; rs[6] = r1.z; rs[7] = r1.w;
            }
            float p0 = 0.f, p1 = 0.f, p2 = 0.f;
#pragma unroll
            for (int j = 0; j < 8; j++) {
                p0 = fmaf(acc[j],  rs[j], p0);
                p1 = fmaf(acc1[j], rs[j], p1);
                p2 = fmaf(xs[j],   rs[j], p2);
            }
            float b0 = quad_sum(p0), b1 = quad_sum(p1), b2 = quad_sum(p2);
            float bl = __ldg(blA + node * 8 + head);

            float s0 = leaky02(bl + b0);
            float s1 = leaky02(bl + b1);
            float s2 = leaky02(bl + b2);
            float mx = fmaxf(s0, fmaxf(s1, s2));
            float w0 = __expf(s0 - mx), w1 = __expf(s1 - mx), w2 = __expf(s2 - mx);
            float inv3 = 1.f / (w0 + w1 + w2);

            float o[8];
#pragma unroll
            for (int j = 0; j < 8; j++)
                o[j] = fmaxf((acc[j] * w0 + acc1[j] * w1 + xs[j] * w2) * inv3, 0.f);
            float4* op = (float4*)(out + (size_t)node * 256);
            op[lane * 2]     = make_float4(o[0], o[1], o[2], o[3]);
            op[lane * 2 + 1] = make_float4(o[4], o[5], o[6], o[7]);
        }
    } else {
        int node = (blockIdx.x - NA_BLK) * 8 + wid;
        float acc[8];
#pragma unroll
        for (int j = 0; j < 8; j++) acc[j] = 0.f;
        float den = 0.f;
        {
            int s = __ldg(rowptr + 2 * RPSTR + node), e = __ldg(rowptr + 2 * RPSTR + node + 1);
            csr_walk(srcs_all + 2 * EED, s, e, al0, head,
                     __ldg(ar0 + node * 8 + head), hA16, lane, acc, den);
        }
        float inv = den > 0.f ? 1.f / den : 0.f;
#pragma unroll
        for (int j = 0; j < 8; j++) acc[j] *= inv;

        float xs[8], rs[8];
        load8f(hB16 + (size_t)node * 256, lane, xs);
        {
            float4 r0 = __ldg((const float4*)rel_r_B + lane * 2);
            float4 r1 = __ldg((const float4*)rel_r_B + lane * 2 + 1);
            rs[0] = r0.x; rs[1] = r0.y; rs[2] = r0.z; rs[3] = r0.w;
            rs[4] = r1.x; rs[5] = r1.y; rs[6] = r1.z; rs[7] = r1.w;
        }
        float p0 = 0.f, p1 = 0.f;
#pragma unroll
        for (int j = 0; j < 8; j++) {
            p0 = fmaf(acc[j], rs[j], p0);
            p1 = fmaf(xs[j],  rs[j], p1);
        }
        float b0 = quad_sum(p0), b1 = quad_sum(p1);
        float bl = __ldg(blB + node * 8 + head);

        float s0 = leaky02(bl + b0);
        float s1 = leaky02(bl + b1);
        float mx = fmaxf(s0, s1);
        float w0 = __expf(s0 - mx), w1 = __expf(s1 - mx);
        float inv2 = 1.f / (w0 + w1);

        float o[8];
#pragma unroll
        for (int j = 0; j < 8; j++)
            o[j] = fmaxf((acc[j] * w0 + xs[j] * w1) * inv2, 0.f);
        float4* op = (float4*)(out + (size_t)(NNA + node) * 256);
        op[lane * 2]     = make_float4(o[0], o[1], o[2], o[3]);
        op[lane * 2 + 1] = make_float4(o[4], o[5], o[6], o[7]);
    }
}

// ---------------- launch ----------------
extern "C" void kernel_launch(void* const* d_in, const int* in_sizes, int n_in,
                              void* d_out, int out_size) {
    const float* x_A     = (const float*)d_in[0];
    const float* x_B     = (const float*)d_in[1];
    const int*   e_ab    = (const int*)d_in[2];
    const int*   e_ba    = (const int*)d_in[3];
    const int*   e_aa    = (const int*)d_in[4];
    const float* W_A     = (const float*)d_in[5];
    const float* b_A     = (const float*)d_in[6];
    const float* W_B     = (const float*)d_in[7];
    const float* b_B     = (const float*)d_in[8];
    const float* attn_l  = (const float*)d_in[9];   // [3,8,32]
    const float* attn_r  = (const float*)d_in[10];
    const float* rel_l_A = (const float*)d_in[11];
    const float* rel_r_A = (const float*)d_in[12];
    const float* rel_l_B = (const float*)d_in[13];
    const float* rel_r_B = (const float*)d_in[14];
    float* out = (float*)d_out;

    void *p_hA16, *p_hB16, *p_W16;
    void *p_al0, *p_ar0, *p_al1, *p_ar1, *p_al2, *p_ar2, *p_blA, *p_blB;
    void *p_srcs, *p_cnt, *p_rowptr, *p_bsum;
    cudaGetSymbolAddress(&p_hA16, g_hA16);
    cudaGetSymbolAddress(&p_hB16, g_hB16);
    cudaGetSymbolAddress(&p_W16, g_W16);
    cudaGetSymbolAddress(&p_al0, g_al0);
    cudaGetSymbolAddress(&p_ar0, g_ar0);
    cudaGetSymbolAddress(&p_al1, g_al1);
    cudaGetSymbolAddress(&p_ar1, g_ar1);
    cudaGetSymbolAddress(&p_al2, g_al2);
    cudaGetSymbolAddress(&p_ar2, g_ar2);
    cudaGetSymbolAddress(&p_blA, g_blA);
    cudaGetSymbolAddress(&p_blB, g_blB);
    cudaGetSymbolAddress(&p_srcs, g_srcs);
    cudaGetSymbolAddress(&p_cnt, g_cnt);
    cudaGetSymbolAddress(&p_rowptr, g_rowptr);
    cudaGetSymbolAddress(&p_bsum, g_blocksum);

    int* cnt    = (int*)p_cnt;
    int* rowptr = (int*)p_rowptr;
    int* srcs   = (int*)p_srcs;
    int* bsum   = (int*)p_bsum;

    // one-time infra (no device memory allocation)
    static cudaStream_t s1 = nullptr;
    static cudaEvent_t evFork = nullptr, evJoin = nullptr;
    if (!s1) {
        cudaStreamCreateWithFlags(&s1, cudaStreamNonBlocking);
        cudaEventCreateWithFlags(&evFork, cudaEventDisableTiming);
        cudaEventCreateWithFlags(&evJoin, cudaEventDisableTiming);
    }

    // fork: sort chain on s1 runs concurrently with wsplit+GEMM on stream 0
    cudaEventRecord(evFork, 0);
    cudaStreamWaitEvent(s1, evFork, 0);
    {
        cudaMemsetAsync(cnt, 0, sizeof(int) * 3 * NNA, s1);
        int g = (EED + 255) / 256;
        count3_kernel<<<g, 256, 0, s1>>>(e_ba, e_aa, e_ab, cnt);
        scan_blocks<<<120, 256, 0, s1>>>(cnt, rowptr, bsum);
        scan_top<<<1, 96, 0, s1>>>(bsum, rowptr);
        scan_add<<<120, 256, 0, s1>>>(rowptr, bsum, cnt);
        scatter3_kernel<<<g, 256, 0, s1>>>(e_ba, e_aa, e_ab, cnt, srcs);
        cudaEventRecord(evJoin, s1);
    }

    // stream 0: W fp16 convert then merged projections (plain fp16 mma)
    {
        dim3 gw(64, 2);
        wsplit_kernel<<<gw, 256>>>(W_A, W_B, (__half*)p_W16);
        dim3 grid((NNA + 127) / 128, 4, 2);
        gemm_fused2<<<grid, 256>>>(x_A, x_B,
                                   (const __half*)p_W16,
                                   b_A, b_B,
                                   (__half*)p_hA16, (__half*)p_hB16,
                                   attn_l, attn_r, rel_l_A, rel_l_B,
                                   (float*)p_al0, (float*)p_ar1,
                                   (float*)p_al2, (float*)p_ar2, (float*)p_blA,
                                   (float*)p_ar0, (float*)p_al1, (float*)p_blB);
    }

    // join: aggbeta needs both the GEMM outputs and the CSR
    cudaStreamWaitEvent(0, evJoin, 0);
    aggbeta_all<<<NA_BLK + NB_BLK, 256>>>(srcs, rowptr,
                                          (float*)p_al1, (float*)p_ar1,
                                          (float*)p_al2, (float*)p_ar2,
                                          (float*)p_al0, (float*)p_ar0,
                                          (const __half*)p_hA16,
                                          (const __half*)p_hB16,
                                          (float*)p_blA, (float*)p_blB,
                                          rel_r_A, rel_r_B, out);

    (void)in_sizes; (void)n_in; (void)out_size;
}